// round 2
// baseline (speedup 1.0000x reference)
#include <cuda_runtime.h>
#include <math.h>

#define NG   128     // graphs
#define NPG  256     // nodes per graph
#define DF   128     // features
#define KB   16      // bins
#define VIEWS 256    // 2 * NG
#define PAIRS 32896  // 256*257/2 (upper tri incl diag)

// Scratch (static device arrays — no allocations)
__device__ float g_D[(size_t)VIEWS * NPG * NPG];   // 64 MB pairwise distances
__device__ __align__(16) float g_zn[VIEWS * DF];   // normalized z
__device__ float g_sig[VIEWS * KB];                // per-view signatures
__device__ float g_ntx[16];                        // ntxent partials

__device__ __forceinline__ int Trow(int i) { return i * NPG - (i * (i - 1)) / 2; }

// ---------------------------------------------------------------------------
// Kernel A: normalize z rows -> g_zn
// ---------------------------------------------------------------------------
__global__ void znorm_kernel(const float* __restrict__ z1, const float* __restrict__ z2) {
    int t = threadIdx.x;  // 256 threads, one row each
    const float* src = (t < NG) ? (z1 + (size_t)t * DF) : (z2 + (size_t)(t - NG) * DF);
    float ss = 0.f;
    #pragma unroll 8
    for (int k = 0; k < DF; k++) { float v = src[k]; ss = fmaf(v, v, ss); }
    float inv = 1.0f / (sqrtf(ss) + 1e-8f);
    #pragma unroll 8
    for (int k = 0; k < DF; k++) g_zn[t * DF + k] = src[k] * inv;
}

// ---------------------------------------------------------------------------
// Kernel C: NT-Xent partials. 16 CTAs x 256 threads; CTA b handles rows
// [16b, 16b+16) of the 256x256 sim matrix.
// smem: zns[256][129] + simbuf[16][256] + rowred[16]
// ---------------------------------------------------------------------------
#define SMEM_C ((256 * 129 + 16 * 256 + 16) * 4)

__global__ __launch_bounds__(256, 1) void ntx_kernel() {
    extern __shared__ float smc[];
    float* zns    = smc;                 // 256 x 129 (padded)
    float* simbuf = zns + 256 * 129;     // 16 x 256
    float* rowred = simbuf + 16 * 256;   // 16

    const int t = threadIdx.x;
    const int rowbase = blockIdx.x * 16;

    // stage normalized z into smem (padded rows)
    const float4* src4 = (const float4*)g_zn;
    #pragma unroll
    for (int m = 0; m < 32; m++) {
        int idx = t + 256 * m;          // float4 idx over 8192
        float4 v = src4[idx];
        int fi = idx * 4;
        int row = fi >> 7, col = fi & 127;
        float* dst = zns + row * 129 + col;
        dst[0] = v.x; dst[1] = v.y; dst[2] = v.z; dst[3] = v.w;
    }
    __syncthreads();

    // 4x4 tile per thread: tx in [0,64) -> cols tx + 64*jj ; ty in [0,4) -> rows ty*4+ii
    const int tx = t & 63, ty = t >> 6;
    float acc[4][4];
    #pragma unroll
    for (int a = 0; a < 4; a++)
        #pragma unroll
        for (int b = 0; b < 4; b++) acc[a][b] = 0.f;

    const float* Ra = zns + (rowbase + ty * 4) * 129;
    const float* Rb = zns + tx * 129;
    #pragma unroll 4
    for (int k = 0; k < DF; k++) {
        float a[4], b[4];
        #pragma unroll
        for (int ii = 0; ii < 4; ii++) a[ii] = Ra[ii * 129 + k];
        #pragma unroll
        for (int jj = 0; jj < 4; jj++) b[jj] = Rb[jj * 64 * 129 + k];
        #pragma unroll
        for (int ii = 0; ii < 4; ii++)
            #pragma unroll
            for (int jj = 0; jj < 4; jj++)
                acc[ii][jj] = fmaf(a[ii], b[jj], acc[ii][jj]);
    }

    #pragma unroll
    for (int ii = 0; ii < 4; ii++) {
        int li = ty * 4 + ii;           // local row
        int gi = rowbase + li;
        #pragma unroll
        for (int jj = 0; jj < 4; jj++) {
            int gj = tx + 64 * jj;
            float s = acc[ii][jj] * 2.0f;      // 1/TEMP
            if (gi == gj) s = -1e9f;
            simbuf[li * 256 + gj] = s;
        }
    }
    __syncthreads();

    // per-row LSE: 8 warps, 2 rows each (deterministic shuffle reductions)
    int w = t >> 5, l = t & 31;
    for (int r = w * 2; r < w * 2 + 2; r++) {
        float mx = -1e30f;
        for (int c = l; c < 256; c += 32) mx = fmaxf(mx, simbuf[r * 256 + c]);
        #pragma unroll
        for (int off = 16; off > 0; off >>= 1)
            mx = fmaxf(mx, __shfl_xor_sync(0xffffffffu, mx, off));
        float se = 0.f;
        for (int c = l; c < 256; c += 32) se += __expf(simbuf[r * 256 + c] - mx);
        #pragma unroll
        for (int off = 16; off > 0; off >>= 1)
            se += __shfl_xor_sync(0xffffffffu, se, off);
        if (l == 0) {
            int gi = rowbase + r;
            int lab = (gi + 128) & 255;
            rowred[r] = simbuf[r * 256 + lab] - (mx + logf(se));  // logp[i,label]
        }
    }
    __syncthreads();
    if (t == 0) {
        float s = 0.f;
        #pragma unroll
        for (int r = 0; r < 16; r++) s += rowred[r];
        g_ntx[blockIdx.x] = s;
    }
}

// ---------------------------------------------------------------------------
// Kernel B (main): one CTA per graph-view. Phase 1: Gram -> D (upper tri) to
// global scratch + mean. Phase 2: soft histogram over normalized distances.
// smem: Hs[256][129] + sq[256] + red[256*16]
// ---------------------------------------------------------------------------
#define SMEM_B ((256 * 129 + 256 + 256 * KB) * 4)

__global__ __launch_bounds__(256, 1) void topo_kernel(const float* __restrict__ H1,
                                                      const float* __restrict__ H2) {
    extern __shared__ float smb[];
    float* Hs  = smb;                 // 256 x 129 (padded)
    float* sq  = Hs + 256 * 129;      // 256 row norms
    float* red = sq + 256;            // 256x16 reduce scratch

    const int t = threadIdx.x;
    const int v = blockIdx.x;
    const float* Hsrc = (v < NG) ? (H1 + (size_t)v * NPG * DF)
                                 : (H2 + (size_t)(v - NG) * NPG * DF);

    // stage H into smem
    const float4* src4 = (const float4*)Hsrc;
    #pragma unroll
    for (int m = 0; m < 32; m++) {
        int idx = t + 256 * m;
        float4 val = src4[idx];
        int fi = idx * 4;
        int row = fi >> 7, col = fi & 127;
        float* dst = Hs + row * 129 + col;
        dst[0] = val.x; dst[1] = val.y; dst[2] = val.z; dst[3] = val.w;
    }
    __syncthreads();

    // row squared norms
    {
        float s = 0.f;
        const float* hr = Hs + t * 129;
        #pragma unroll 8
        for (int k = 0; k < DF; k++) s = fmaf(hr[k], hr[k], s);
        sq[t] = s;
    }
    __syncthreads();

    // Phase 1: Gram in 3 quadrant passes (skip strictly-lower quadrant)
    float lsum = 0.f;
    const int tx = t & 15, ty = t >> 4;
    float* gD = g_D + (size_t)v * (NPG * NPG);

    for (int ps = 0; ps < 3; ps++) {
        const int rb = (ps == 2) ? 128 : 0;
        const int cb = (ps == 0) ? 0 : 128;
        float acc[8][8];
        #pragma unroll
        for (int a = 0; a < 8; a++)
            #pragma unroll
            for (int b = 0; b < 8; b++) acc[a][b] = 0.f;

        const float* Ra = Hs + (rb + ty) * 129;
        const float* Rb = Hs + (cb + tx) * 129;
        #pragma unroll 4
        for (int k = 0; k < DF; k++) {
            float a[8], b[8];
            #pragma unroll
            for (int ii = 0; ii < 8; ii++) a[ii] = Ra[ii * 16 * 129 + k];
            #pragma unroll
            for (int jj = 0; jj < 8; jj++) b[jj] = Rb[jj * 16 * 129 + k];
            #pragma unroll
            for (int ii = 0; ii < 8; ii++)
                #pragma unroll
                for (int jj = 0; jj < 8; jj++)
                    acc[ii][jj] = fmaf(a[ii], b[jj], acc[ii][jj]);
        }

        #pragma unroll
        for (int ii = 0; ii < 8; ii++) {
            int i = rb + ty + 16 * ii;
            #pragma unroll
            for (int jj = 0; jj < 8; jj++) {
                int j = cb + tx + 16 * jj;
                if (j >= i) {
                    float d2 = sq[i] + sq[j] - 2.0f * acc[ii][jj];
                    float d  = sqrtf(fmaxf(d2, 0.0f) + 1e-12f);
                    lsum += (j > i) ? 2.0f * d : d;
                    gD[i * NPG + j] = d;
                }
            }
        }
    }

    // block reduce sum of D (deterministic tree)
    red[t] = lsum;
    __syncthreads();
    for (int s = 128; s > 0; s >>= 1) {
        if (t < s) red[t] += red[t + s];
        __syncthreads();
    }
    float invm = 1.0f / (red[0] * (1.0f / 65536.0f) + 1e-8f);
    __syncthreads();  // before reusing red as hist buffer

    // Phase 2: soft histogram. w_k = exp2(-(x*Sc - ck*Sc)^2), Sc^2 = 0.5*log2e/sigma^2
    const float Sc = 4.5297165f;     // sqrt(0.5*log2(e)) / (3/16)
    const float CS = 0.2f * Sc;      // center spacing * Sc
    float hist[KB];
    #pragma unroll
    for (int k = 0; k < KB; k++) hist[k] = 0.f;

    for (int p = t; p < PAIRS; p += 256) {
        int i = (int)((513.0f - sqrtf(263169.0f - 8.0f * (float)p)) * 0.5f);
        if (i < 0) i = 0; if (i > 255) i = 255;
        while (Trow(i + 1) <= p) i++;
        while (Trow(i) > p) i--;
        int j = i + (p - Trow(i));

        float d = gD[i * NPG + j];
        float xs = d * invm * Sc;
        float wt = (j > i) ? 2.0f : 1.0f;
        #pragma unroll
        for (int k = 0; k < KB; k++) {
            float u = xs - CS * (float)k;
            float w = exp2f(-u * u);
            hist[k] = fmaf(wt, w, hist[k]);
        }
    }

    // deterministic hist reduction over 256 threads
    float* hb = red;  // 256 x 16
    #pragma unroll
    for (int k = 0; k < KB; k++) hb[t * KB + k] = hist[k];
    __syncthreads();
    for (int s = 128; s > 0; s >>= 1) {
        if (t < s) {
            #pragma unroll
            for (int k = 0; k < KB; k++) hb[t * KB + k] += hb[(t + s) * KB + k];
        }
        __syncthreads();
    }
    if (t == 0) {
        float tot = 0.f;
        #pragma unroll
        for (int k = 0; k < KB; k++) tot += hb[k];
        float inv = 1.0f / (tot + 1e-8f);
        #pragma unroll
        for (int k = 0; k < KB; k++) g_sig[v * KB + k] = hb[k] * inv;
    }
}

// ---------------------------------------------------------------------------
// Kernel D: final combine -> scalar loss
// ---------------------------------------------------------------------------
__global__ void final_kernel(float* __restrict__ out) {
    __shared__ float red[256];
    int t = threadIdx.x;
    float val = 0.f;
    if (t < NG) {
        float s = 0.f;
        #pragma unroll
        for (int k = 0; k < KB; k++) {
            float d = g_sig[t * KB + k] - g_sig[(NG + t) * KB + k];
            s = fmaf(d, d, s);
        }
        val = s * (1.0f / (float)KB);
    }
    red[t] = val;
    __syncthreads();
    for (int s = 128; s > 0; s >>= 1) {
        if (t < s) red[t] += red[t + s];
        __syncthreads();
    }
    if (t == 0) {
        float topo = red[0] / (float)NG;
        float slogp = 0.f;
        #pragma unroll
        for (int i = 0; i < 16; i++) slogp += g_ntx[i];
        float ntxent = -slogp / 256.0f;
        out[0] = 0.1f * (topo + ntxent);
    }
}

// ---------------------------------------------------------------------------
extern "C" void kernel_launch(void* const* d_in, const int* in_sizes, int n_in,
                              void* d_out, int out_size) {
    const float* H1 = (const float*)d_in[0];
    const float* H2 = (const float*)d_in[2];
    const float* z1 = (const float*)d_in[4];
    const float* z2 = (const float*)d_in[5];
    float* out = (float*)d_out;

    cudaFuncSetAttribute(topo_kernel, cudaFuncAttributeMaxDynamicSharedMemorySize, SMEM_B);
    cudaFuncSetAttribute(ntx_kernel,  cudaFuncAttributeMaxDynamicSharedMemorySize, SMEM_C);

    znorm_kernel<<<1, 256>>>(z1, z2);
    ntx_kernel<<<16, 256, SMEM_C>>>();
    topo_kernel<<<VIEWS, 256, SMEM_B>>>(H1, H2);
    final_kernel<<<1, 256>>>(out);
}

// round 3
// speedup vs baseline: 2.2608x; 2.2608x over previous
#include <cuda_runtime.h>
#include <cuda_fp16.h>
#include <math.h>

#define NG   128
#define NPG  256
#define DF   128
#define KB   16
#define VIEWS 256
#define SUP  32640          // strict-upper pairs 256*255/2
#define HSS  257            // HsT row stride (floats)
#define GRID_TOTAL (VIEWS + 16)

// smem layout (float offsets) for topo CTAs
#define F_SQ   (DF*HSS)           // 32896
#define F_RED  (F_SQ + NPG)       // 33152
#define F_DH   (F_RED + NPG*KB)   // 37248 ; holds SUP halves = SUP/2 floats
#define SMEM_FLOATS (F_DH + SUP/2)
#define SMEM_BYTES  (SMEM_FLOATS * 4)   // 214272 B

typedef unsigned long long u64;

__device__ unsigned g_done = 0;
__device__ float g_sig[VIEWS * KB];
__device__ float g_ntx[16];

__device__ __forceinline__ float ex2f(float x) {
    float r; asm("ex2.approx.f32 %0, %1;" : "=f"(r) : "f"(x)); return r;
}
__device__ __forceinline__ float sqrt_apx(float x) {
    float r; asm("sqrt.approx.f32 %0, %1;" : "=f"(r) : "f"(x)); return r;
}
__device__ __forceinline__ u64 pack2(float lo, float hi) {
    u64 r;
    asm("mov.b64 %0, {%1, %2};" : "=l"(r)
        : "r"(__float_as_uint(lo)), "r"(__float_as_uint(hi)));
    return r;
}
__device__ __forceinline__ void unpack2(u64 v, float& lo, float& hi) {
    unsigned a, b;
    asm("mov.b64 {%0, %1}, %2;" : "=r"(a), "=r"(b) : "l"(v));
    lo = __uint_as_float(a); hi = __uint_as_float(b);
}
__device__ __forceinline__ void ffma2(u64& d, u64 a, u64 b) {
    asm("fma.rn.f32x2 %0, %1, %2, %0;" : "+l"(d) : "l"(a), "l"(b));
}

// ---------------------------------------------------------------------------
// One Gram quadrant pass with packed f32x2 FMA.
// Threads: (tx,ty) in 16x16; thread covers rows rb+ty+16*ii, cols cb+tx+16*jj.
// DIAG=true: diagonal quadrant — compute only jj-pairs with 2q+1 >= ii
// (covers all strict-upper elements), write only j > i.
// ---------------------------------------------------------------------------
template<bool DIAG>
__device__ __forceinline__ void gram_pass(const float* __restrict__ HsT,
                                          const float* __restrict__ sq,
                                          __half* __restrict__ Dh,
                                          float& lsum, int rb, int cb,
                                          int tx, int ty)
{
    u64 acc[8][4];
    #pragma unroll
    for (int i = 0; i < 8; i++)
        #pragma unroll
        for (int q = 0; q < 4; q++) acc[i][q] = 0ull;

    const int ra0 = rb + ty;
    const int cb0 = cb + tx;
    #pragma unroll 4
    for (int k = 0; k < DF; k++) {
        const float* row = HsT + k * HSS;
        float a[8], b[8];
        #pragma unroll
        for (int ii = 0; ii < 8; ii++) a[ii] = row[ra0 + 16 * ii];
        #pragma unroll
        for (int jj = 0; jj < 8; jj++) b[jj] = row[cb0 + 16 * jj];
        u64 a2[8], b2[4];
        #pragma unroll
        for (int ii = 0; ii < 8; ii++) a2[ii] = pack2(a[ii], a[ii]);
        #pragma unroll
        for (int q = 0; q < 4; q++) b2[q] = pack2(b[2 * q], b[2 * q + 1]);
        #pragma unroll
        for (int ii = 0; ii < 8; ii++)
            #pragma unroll
            for (int q = 0; q < 4; q++)
                if (!DIAG || (2 * q + 1) >= ii)
                    ffma2(acc[ii][q], a2[ii], b2[q]);
    }

    // epilogue: d = sqrt(max(sqi+sqj-2dot,0)+1e-12); store fp16 strict-upper packed
    #pragma unroll
    for (int ii = 0; ii < 8; ii++) {
        int i = rb + ty + 16 * ii;
        float sqi = sq[i];
        int trow = 255 * i - ((i * (i - 1)) >> 1) - i - 1;  // + j gives packed idx
        #pragma unroll
        for (int q = 0; q < 4; q++) {
            if (DIAG && (2 * q + 1) < ii) continue;
            float lo, hi; unpack2(acc[ii][q], lo, hi);
            int j0 = cb + tx + 32 * q;
            int j1 = j0 + 16;
            if (j0 > i) {
                float d2 = sq[j0] + sqi - 2.0f * lo;
                float d = sqrt_apx(fmaxf(d2, 0.0f) + 1e-12f);
                lsum += d;
                Dh[trow + j0] = __float2half(d);
            }
            if (j1 > i) {
                float d2 = sq[j1] + sqi - 2.0f * hi;
                float d = sqrt_apx(fmaxf(d2, 0.0f) + 1e-12f);
                lsum += d;
                Dh[trow + j1] = __float2half(d);
            }
        }
    }
}

// ---------------------------------------------------------------------------
// Topo body: one CTA per graph-view.
// ---------------------------------------------------------------------------
__device__ __forceinline__ void topo_body(float* sm, int t, int v,
                                          const float* __restrict__ H1,
                                          const float* __restrict__ H2)
{
    float* HsT = sm;
    float* sq  = sm + F_SQ;
    float* red = sm + F_RED;
    __half* Dh = (__half*)(sm + F_DH);

    const float* Hsrc = (v < NG) ? (H1 + (size_t)v * NPG * DF)
                                 : (H2 + (size_t)(v - NG) * NPG * DF);

    // stage H transposed: HsT[k][node]; thread t owns node row t; compute sq on the fly
    {
        const float4* src = (const float4*)(Hsrc + (size_t)t * DF);
        float ss = 0.f;
        #pragma unroll
        for (int m = 0; m < 32; m++) {
            float4 val = src[m];
            int k = 4 * m;
            HsT[(k    ) * HSS + t] = val.x;
            HsT[(k + 1) * HSS + t] = val.y;
            HsT[(k + 2) * HSS + t] = val.z;
            HsT[(k + 3) * HSS + t] = val.w;
            ss = fmaf(val.x, val.x, ss);
            ss = fmaf(val.y, val.y, ss);
            ss = fmaf(val.z, val.z, ss);
            ss = fmaf(val.w, val.w, ss);
        }
        sq[t] = ss;
    }
    __syncthreads();

    const int tx = t & 15, ty = t >> 4;
    float lsum = 0.f;
    gram_pass<false>(HsT, sq, Dh, lsum, 0,   128, tx, ty);  // off-diag quadrant
    gram_pass<true >(HsT, sq, Dh, lsum, 0,   0,   tx, ty);  // diag quadrant 0
    gram_pass<true >(HsT, sq, Dh, lsum, 128, 128, tx, ty);  // diag quadrant 1
    __syncthreads();

    // mean of D over full 256x256 (strict-upper*2 + 256 diag entries of 1e-6)
    red[t] = lsum;
    __syncthreads();
    for (int s = 128; s > 0; s >>= 1) {
        if (t < s) red[t] += red[t + s];
        __syncthreads();
    }
    float S_all = 2.0f * red[0] + 256.0f * 1e-6f;
    float mean  = S_all * (1.0f / 65536.0f);
    float invm  = 1.0f / (mean + 1e-8f);
    __syncthreads();   // before reusing red as histogram buffer

    // Phase 2: soft histogram via exp2 recurrence, dual anchors k=0 and k=8.
    // w_k = exp2(-(xs - CS*k)^2), xs = Dn*Sc ; w_k = w_{k-1} * E_k * R,
    // E_k = exp2(-CS^2*(2k-1)) const, R = exp2(2*CS*xs).
    const float SIG = 0.1875f;
    const float S2  = 0.72134752f / (SIG * SIG);   // 0.5*log2(e)/sigma^2
    const float Sc  = sqrtf(S2);
    const float CS  = 0.2f * Sc;
    const float CS2 = CS * CS;
    const float TCS = 2.0f * CS;
    const float C8  = 8.0f * CS;
    float E[15];
    #pragma unroll
    for (int k = 1; k <= 15; k++) E[k - 1] = ex2f(-CS2 * (float)(2 * k - 1));
    const float invmSc = invm * Sc;

    float hA[KB], hB[KB];
    #pragma unroll
    for (int k = 0; k < KB; k++) { hA[k] = 0.f; hB[k] = 0.f; }

    const __half2* Dp = (const __half2*)Dh;
    const int nh = SUP / 2;   // 16320 half2 elements
    for (int m = 0; m < 64; m++) {
        int idx = t + 256 * m;
        if (idx < nh) {
            float2 dd = __half22float2(Dp[idx]);
            float xa = dd.x * invmSc, xb = dd.y * invmSc;
            float wa = ex2f(-xa * xa), wb = ex2f(-xb * xb);
            float Ra = ex2f(TCS * xa), Rb = ex2f(TCS * xb);
            float ua = xa - C8,        ub = xb - C8;
            float va = ex2f(-ua * ua), vb = ex2f(-ub * ub);
            hA[0] += wa; hB[0] += wb;
            #pragma unroll
            for (int k = 1; k < 8; k++) {
                wa = wa * E[k - 1] * Ra; wb = wb * E[k - 1] * Rb;
                hA[k] += wa; hB[k] += wb;
            }
            hA[8] += va; hB[8] += vb;
            #pragma unroll
            for (int k = 9; k < 16; k++) {
                va = va * E[k - 1] * Ra; vb = vb * E[k - 1] * Rb;
                hA[k] += va; hB[k] += vb;
            }
        }
    }

    // deterministic histogram reduction (256 x 16)
    float* hb = red;
    #pragma unroll
    for (int k = 0; k < KB; k++) hb[t * KB + k] = hA[k] + hB[k];
    __syncthreads();
    for (int s = 128; s > 0; s >>= 1) {
        if (t < s) {
            #pragma unroll
            for (int k = 0; k < KB; k++) hb[t * KB + k] += hb[(t + s) * KB + k];
        }
        __syncthreads();
    }
    if (t == 0) {
        float xd = 1e-6f * invmSc;   // normalized diagonal distance
        float bins[KB];
        float tot = 0.f;
        #pragma unroll
        for (int k = 0; k < KB; k++) {
            float u = xd - CS * (float)k;
            bins[k] = 2.0f * hb[k] + 256.0f * ex2f(-u * u);
            tot += bins[k];
        }
        float inv = 1.0f / (tot + 1e-8f);
        #pragma unroll
        for (int k = 0; k < KB; k++) g_sig[v * KB + k] = bins[k] * inv;
    }
}

// ---------------------------------------------------------------------------
// NT-Xent body: CTA b handles rows [16b,16b+16) of the 256x256 sim matrix.
// ---------------------------------------------------------------------------
__device__ __forceinline__ void ntx_body(float* sm, int t, int b,
                                         const float* __restrict__ z1,
                                         const float* __restrict__ z2)
{
    float* zns    = sm;                  // 256 x 129 padded
    float* simbuf = zns + 256 * 129;     // 16 x 256
    float* rowred = simbuf + 16 * 256;   // 16

    // normalize z row t into smem
    const float* zsrc = (t < NG) ? (z1 + (size_t)t * DF) : (z2 + (size_t)(t - NG) * DF);
    float ss = 0.f;
    #pragma unroll 8
    for (int k = 0; k < DF; k++) { float x = zsrc[k]; ss = fmaf(x, x, ss); }
    float inv = 1.0f / (sqrtf(ss) + 1e-8f);
    #pragma unroll 8
    for (int k = 0; k < DF; k++) zns[t * 129 + k] = zsrc[k] * inv;
    __syncthreads();

    const int rowbase = b * 16;
    const int tx = t & 63, ty = t >> 6;
    float acc[4][4];
    #pragma unroll
    for (int a = 0; a < 4; a++)
        #pragma unroll
        for (int c = 0; c < 4; c++) acc[a][c] = 0.f;

    const float* Ra = zns + (rowbase + ty * 4) * 129;
    const float* Rb = zns + tx * 129;
    #pragma unroll 4
    for (int k = 0; k < DF; k++) {
        float a[4], bb[4];
        #pragma unroll
        for (int ii = 0; ii < 4; ii++) a[ii] = Ra[ii * 129 + k];
        #pragma unroll
        for (int jj = 0; jj < 4; jj++) bb[jj] = Rb[jj * 64 * 129 + k];
        #pragma unroll
        for (int ii = 0; ii < 4; ii++)
            #pragma unroll
            for (int jj = 0; jj < 4; jj++)
                acc[ii][jj] = fmaf(a[ii], bb[jj], acc[ii][jj]);
    }

    #pragma unroll
    for (int ii = 0; ii < 4; ii++) {
        int li = ty * 4 + ii;
        int gi = rowbase + li;
        #pragma unroll
        for (int jj = 0; jj < 4; jj++) {
            int gj = tx + 64 * jj;
            float s = acc[ii][jj] * 2.0f;   // 1/TEMP
            if (gi == gj) s = -1e9f;
            simbuf[li * 256 + gj] = s;
        }
    }
    __syncthreads();

    int w = t >> 5, l = t & 31;
    for (int r = w * 2; r < w * 2 + 2; r++) {
        float mx = -1e30f;
        for (int c = l; c < 256; c += 32) mx = fmaxf(mx, simbuf[r * 256 + c]);
        #pragma unroll
        for (int off = 16; off > 0; off >>= 1)
            mx = fmaxf(mx, __shfl_xor_sync(0xffffffffu, mx, off));
        float se = 0.f;
        for (int c = l; c < 256; c += 32) se += __expf(simbuf[r * 256 + c] - mx);
        #pragma unroll
        for (int off = 16; off > 0; off >>= 1)
            se += __shfl_xor_sync(0xffffffffu, se, off);
        if (l == 0) {
            int gi = rowbase + r;
            int lab = (gi + 128) & 255;
            rowred[r] = simbuf[r * 256 + lab] - (mx + logf(se));
        }
    }
    __syncthreads();
    if (t == 0) {
        float s = 0.f;
        #pragma unroll
        for (int r = 0; r < 16; r++) s += rowred[r];
        g_ntx[b] = s;
    }
}

// ---------------------------------------------------------------------------
// Fused kernel: 256 topo CTAs + 16 ntx CTAs; last-arriving CTA does the final
// combine (deterministic: fixed-order sums, single writer).
// ---------------------------------------------------------------------------
__global__ __launch_bounds__(256, 1) void fused_kernel(const float* __restrict__ H1,
                                                       const float* __restrict__ H2,
                                                       const float* __restrict__ z1,
                                                       const float* __restrict__ z2,
                                                       float* __restrict__ out)
{
    extern __shared__ float sm[];
    __shared__ unsigned rank_s;
    const int t = threadIdx.x;
    const int v = blockIdx.x;

    if (v < VIEWS) topo_body(sm, t, v, H1, H2);
    else           ntx_body(sm, t, v - VIEWS, z1, z2);

    __syncthreads();
    if (t == 0) {
        __threadfence();
        rank_s = atomicAdd(&g_done, 1u);
    }
    __syncthreads();

    if (rank_s == GRID_TOTAL - 1) {
        __threadfence();
        float* red2 = sm;   // this CTA is done with its smem
        float val = 0.f;
        if (t < NG) {
            float s = 0.f;
            #pragma unroll
            for (int k = 0; k < KB; k++) {
                float d = __ldcg(&g_sig[t * KB + k]) - __ldcg(&g_sig[(NG + t) * KB + k]);
                s = fmaf(d, d, s);
            }
            val = s * (1.0f / (float)KB);
        }
        red2[t] = val;
        __syncthreads();
        for (int s = 128; s > 0; s >>= 1) {
            if (t < s) red2[t] += red2[t + s];
            __syncthreads();
        }
        if (t == 0) {
            float topo = red2[0] / (float)NG;
            float sn = 0.f;
            #pragma unroll
            for (int i = 0; i < 16; i++) sn += __ldcg(&g_ntx[i]);
            out[0] = 0.1f * (topo - sn / 256.0f);
            g_done = 0;   // reset for next graph replay
        }
    }
}

// ---------------------------------------------------------------------------
extern "C" void kernel_launch(void* const* d_in, const int* in_sizes, int n_in,
                              void* d_out, int out_size) {
    const float* H1 = (const float*)d_in[0];
    const float* H2 = (const float*)d_in[2];
    const float* z1 = (const float*)d_in[4];
    const float* z2 = (const float*)d_in[5];
    float* out = (float*)d_out;

    cudaFuncSetAttribute(fused_kernel, cudaFuncAttributeMaxDynamicSharedMemorySize, SMEM_BYTES);
    fused_kernel<<<GRID_TOTAL, 256, SMEM_BYTES>>>(H1, H2, z1, z2, out);
}

// round 7
// speedup vs baseline: 3.7755x; 1.6700x over previous
#include <cuda_runtime.h>
#include <cuda_bf16.h>
#include <math.h>
#include <stdint.h>

#define NG   128
#define NPG  256
#define DF   128
#define KB   16
#define VIEWS 256
#define GRID_TOTAL (VIEWS + 16)

#define HST 132              // topo bf16 row stride (halves); 264B rows, 8B aligned
#define ZST 133              // ntx fp32 row stride (conflict-free: 133 % 32 = 5)

// topo smem layout (float offsets)
#define F_H    0             // 256*132 halves = 16896 floats (reused as reduce buf later)
#define F_CNT  16896         // 8*256 u32 per-warp counters
#define F_SQ   18944         // 256 floats
// ntx smem layout
#define N_RA   0             // 16*133 = 2128
#define N_ZB   2128          // 128*133 = 17024
#define N_SIM  19152         // 16*256 = 4096
#define N_RR   23248         // 16
#define SMEM_FLOATS 23264
#define SMEM_BYTES  (SMEM_FLOATS * 4)   // 93056 B -> 2 CTAs/SM

typedef unsigned u32;

__device__ unsigned g_done = 0;
__device__ float g_sig[VIEWS * KB];
__device__ float g_ntx[16];

__device__ __forceinline__ float ex2f(float x) {
    float r; asm("ex2.approx.f32 %0, %1;" : "=f"(r) : "f"(x)); return r;
}
__device__ __forceinline__ __nv_bfloat162 as_bf2(u32 w) {
    return *reinterpret_cast<__nv_bfloat162*>(&w);
}

// ---------------------------------------------------------------------------
// Gram quadrant pass, bf16 HFMA2 with k-split packing.
// rows rb+ty+16*ii, cols cb+tx+16*jj ; DIAG: compute cells jj>=ii only,
// emit entries with j>i.
// ---------------------------------------------------------------------------
template<bool DIAG>
__device__ __forceinline__ void gram_pass(const __nv_bfloat16* __restrict__ Hb,
                                          const float* __restrict__ sq,
                                          u32* __restrict__ cnt,
                                          int rb, int cb, int tx, int ty, int wid)
{
    __nv_bfloat162 acc[8][8];
    #pragma unroll
    for (int i = 0; i < 8; i++)
        #pragma unroll
        for (int j = 0; j < 8; j++) acc[i][j] = __nv_bfloat162(__float2bfloat16(0.f),
                                                               __float2bfloat16(0.f));
    const int r0 = rb + ty;
    const int c0 = cb + tx;

    for (int kk = 0; kk < DF; kk += 4) {
        uint2 A[8], B[8];
        #pragma unroll
        for (int ii = 0; ii < 8; ii++)
            A[ii] = *(const uint2*)(Hb + (size_t)(r0 + 16 * ii) * HST + kk);
        #pragma unroll
        for (int jj = 0; jj < 8; jj++)
            B[jj] = *(const uint2*)(Hb + (size_t)(c0 + 16 * jj) * HST + kk);
        #pragma unroll
        for (int ii = 0; ii < 8; ii++)
            #pragma unroll
            for (int jj = 0; jj < 8; jj++)
                if (!DIAG || jj >= ii) {
                    acc[ii][jj] = __hfma2(as_bf2(A[ii].x), as_bf2(B[jj].x), acc[ii][jj]);
                    acc[ii][jj] = __hfma2(as_bf2(A[ii].y), as_bf2(B[jj].y), acc[ii][jj]);
                }
    }

    // epilogue: d^2 -> u8 quant -> per-warp count
    u32* mycnt = cnt + wid * 256;
    #pragma unroll
    for (int ii = 0; ii < 8; ii++) {
        int i = r0 + 16 * ii;
        float sqi = sq[i];
        #pragma unroll
        for (int jj = 0; jj < 8; jj++) {
            if (DIAG && jj < ii) continue;
            int j = c0 + 16 * jj;
            if (!DIAG || j > i) {
                float2 f = __bfloat1622float2(acc[ii][jj]);
                float dot = f.x + f.y;
                float d2 = fmaxf(fmaf(-2.0f, dot, sqi + sq[j]), 0.0f);
                u32 q = __float2uint_rn(d2 * 0.25f);
                q = min(q, 255u);
                atomicAdd(&mycnt[q], 1u);
            }
        }
    }
}

// ---------------------------------------------------------------------------
// Topo body: one CTA per graph-view.
// ---------------------------------------------------------------------------
__device__ __forceinline__ void topo_body(float* sm, int t, int v,
                                          const float* __restrict__ H1,
                                          const float* __restrict__ H2)
{
    __nv_bfloat16* Hb = (__nv_bfloat16*)sm;
    u32*   cnt = (u32*)(sm + F_CNT);
    float* sq  = sm + F_SQ;
    float* red = sm;                       // aliases Hb; used only after Gram

    const int wid = t >> 5;
    const int tx = t & 15, ty = t >> 4;

    // zero per-warp counters
    #pragma unroll
    for (int i = 0; i < 8; i++) cnt[t + 256 * i] = 0;

    const float* Hsrc = (v < NG) ? (H1 + (size_t)v * NPG * DF)
                                 : (H2 + (size_t)(v - NG) * NPG * DF);

    // stage row t as bf16 [node][k]; fp32 row norms
    {
        const float4* src = (const float4*)(Hsrc + (size_t)t * DF);
        __nv_bfloat16* dst = Hb + (size_t)t * HST;
        float ss = 0.f;
        #pragma unroll
        for (int m = 0; m < 32; m++) {
            float4 val = src[m];
            ss = fmaf(val.x, val.x, ss); ss = fmaf(val.y, val.y, ss);
            ss = fmaf(val.z, val.z, ss); ss = fmaf(val.w, val.w, ss);
            __nv_bfloat162 p0 = __floats2bfloat162_rn(val.x, val.y);
            __nv_bfloat162 p1 = __floats2bfloat162_rn(val.z, val.w);
            uint2 w;
            w.x = *(u32*)&p0; w.y = *(u32*)&p1;
            *(uint2*)(dst + 4 * m) = w;
        }
        sq[t] = ss;
    }
    __syncthreads();

    gram_pass<false>(Hb, sq, cnt, 0,   128, tx, ty, wid);
    gram_pass<true >(Hb, sq, cnt, 0,   0,   tx, ty, wid);
    gram_pass<true >(Hb, sq, cnt, 128, 128, tx, ty, wid);
    __syncthreads();

    // merge per-warp counters; mean from quantized distances d_q = 2*sqrt(q)
    u32 c_t = 0;
    #pragma unroll
    for (int w = 0; w < 8; w++) c_t += cnt[w * 256 + t];
    float rt2 = 2.0f * sqrtf((float)t);
    red[t] = (float)c_t * rt2;
    __syncthreads();
    for (int s = 128; s > 0; s >>= 1) {
        if (t < s) red[t] += red[t + s];
        __syncthreads();
    }
    float mean = (2.0f * red[0] + 2.56e-4f) * (1.0f / 65536.0f);
    const float Sc = 4.5297165f;           // sqrt(0.5*log2e)/sigma, sigma = 3/16
    const float CS = 0.2f * Sc;
    float invmSc = Sc / (mean + 1e-8f);
    __syncthreads();                       // before reusing red

    // per-q bin weights (16 exp2 per thread, scaled by count)
    float xs = rt2 * invmSc;
    float fc = (float)c_t;
    #pragma unroll
    for (int k = 0; k < KB; k++) {
        float u = xs - CS * (float)k;
        red[t * KB + k] = fc * ex2f(-u * u);
    }
    __syncthreads();
    for (int s = 128; s > 0; s >>= 1) {
        if (t < s) {
            #pragma unroll
            for (int k = 0; k < KB; k++) red[t * KB + k] += red[(t + s) * KB + k];
        }
        __syncthreads();
    }
    if (t == 0) {
        float xd = 1e-6f * invmSc;         // normalized diagonal distance
        float tot = 0.f, bins[KB];
        #pragma unroll
        for (int k = 0; k < KB; k++) {
            float u = xd - CS * (float)k;
            bins[k] = 2.0f * red[k] + 256.0f * ex2f(-u * u);
            tot += bins[k];
        }
        float inv = 1.0f / (tot + 1e-8f);
        #pragma unroll
        for (int k = 0; k < KB; k++) g_sig[v * KB + k] = bins[k] * inv;
    }
}

// ---------------------------------------------------------------------------
// NT-Xent body: CTA b -> sim rows [16b,16b+16); cols staged in 2 passes.
// ---------------------------------------------------------------------------
__device__ __forceinline__ void ntx_norm_row(const float* __restrict__ z1,
                                             const float* __restrict__ z2,
                                             int r, float* dst)
{
    const float* src = (r < NG) ? (z1 + (size_t)r * DF) : (z2 + (size_t)(r - NG) * DF);
    float ss = 0.f;
    #pragma unroll 8
    for (int k = 0; k < DF; k++) { float x = src[k]; ss = fmaf(x, x, ss); }
    float inv = 1.0f / (sqrtf(ss) + 1e-8f);
    #pragma unroll 8
    for (int k = 0; k < DF; k++) dst[k] = src[k] * inv;
}

__device__ __forceinline__ void ntx_body(float* sm, int t, int b,
                                         const float* __restrict__ z1,
                                         const float* __restrict__ z2)
{
    float* Ra     = sm + N_RA;
    float* Zb     = sm + N_ZB;
    float* simbuf = sm + N_SIM;
    float* rowred = sm + N_RR;
    const int rowbase = b * 16;
    const int tx = t & 31, ty = t >> 5;

    for (int p = 0; p < 2; p++) {
        if (p) __syncthreads();            // Zb reuse barrier
        if (t < 128)               ntx_norm_row(z1, z2, 128 * p + t, Zb + (size_t)t * ZST);
        if (p == 0 && t >= 128 && t < 144)
            ntx_norm_row(z1, z2, rowbase + (t - 128), Ra + (size_t)(t - 128) * ZST);
        __syncthreads();

        float acc[2][4];
        #pragma unroll
        for (int a = 0; a < 2; a++)
            #pragma unroll
            for (int c = 0; c < 4; c++) acc[a][c] = 0.f;

        const float* ra0 = Ra + (size_t)(2 * ty) * ZST;
        const float* ra1 = ra0 + ZST;
        #pragma unroll 4
        for (int k = 0; k < DF; k++) {
            float a0 = ra0[k], a1 = ra1[k];
            #pragma unroll
            for (int jj = 0; jj < 4; jj++) {
                float bb = Zb[(size_t)(tx + 32 * jj) * ZST + k];
                acc[0][jj] = fmaf(a0, bb, acc[0][jj]);
                acc[1][jj] = fmaf(a1, bb, acc[1][jj]);
            }
        }
        #pragma unroll
        for (int a = 0; a < 2; a++) {
            int li = 2 * ty + a;
            int gi = rowbase + li;
            #pragma unroll
            for (int jj = 0; jj < 4; jj++) {
                int gj = 128 * p + tx + 32 * jj;
                float s = acc[a][jj] * 2.0f;     // 1/TEMP
                if (gi == gj) s = -1e9f;
                simbuf[li * 256 + gj] = s;
            }
        }
    }
    __syncthreads();

    int w = t >> 5, l = t & 31;
    for (int r = w * 2; r < w * 2 + 2; r++) {
        float mx = -1e30f;
        for (int c = l; c < 256; c += 32) mx = fmaxf(mx, simbuf[r * 256 + c]);
        #pragma unroll
        for (int off = 16; off > 0; off >>= 1)
            mx = fmaxf(mx, __shfl_xor_sync(0xffffffffu, mx, off));
        float se = 0.f;
        for (int c = l; c < 256; c += 32) se += __expf(simbuf[r * 256 + c] - mx);
        #pragma unroll
        for (int off = 16; off > 0; off >>= 1)
            se += __shfl_xor_sync(0xffffffffu, se, off);
        if (l == 0) {
            int gi = rowbase + r;
            int lab = (gi + 128) & 255;
            rowred[r] = simbuf[r * 256 + lab] - (mx + logf(se));
        }
    }
    __syncthreads();
    if (t == 0) {
        float s = 0.f;
        #pragma unroll
        for (int r = 0; r < 16; r++) s += rowred[r];
        g_ntx[b] = s;
    }
}

// ---------------------------------------------------------------------------
__global__ __launch_bounds__(256, 2) void fused_kernel(const float* __restrict__ H1,
                                                       const float* __restrict__ H2,
                                                       const float* __restrict__ z1,
                                                       const float* __restrict__ z2,
                                                       float* __restrict__ out)
{
    extern __shared__ float sm[];
    __shared__ unsigned rank_s;
    const int t = threadIdx.x;
    const int v = blockIdx.x;

    if (v < VIEWS) topo_body(sm, t, v, H1, H2);
    else           ntx_body(sm, t, v - VIEWS, z1, z2);

    __syncthreads();
    if (t == 0) {
        __threadfence();
        rank_s = atomicAdd(&g_done, 1u);
    }
    __syncthreads();

    if (rank_s == GRID_TOTAL - 1) {
        __threadfence();
        float* red2 = sm;
        float val = 0.f;
        if (t < NG) {
            float s = 0.f;
            #pragma unroll
            for (int k = 0; k < KB; k++) {
                float d = __ldcg(&g_sig[t * KB + k]) - __ldcg(&g_sig[(NG + t) * KB + k]);
                s = fmaf(d, d, s);
            }
            val = s * (1.0f / (float)KB);
        }
        red2[t] = val;
        __syncthreads();
        for (int s = 128; s > 0; s >>= 1) {
            if (t < s) red2[t] += red2[t + s];
            __syncthreads();
        }
        if (t == 0) {
            float topo = red2[0] / (float)NG;
            float sn = 0.f;
            #pragma unroll
            for (int i = 0; i < 16; i++) sn += __ldcg(&g_ntx[i]);
            out[0] = 0.1f * (topo - sn / 256.0f);
            g_done = 0;
        }
    }
}

// ---------------------------------------------------------------------------
extern "C" void kernel_launch(void* const* d_in, const int* in_sizes, int n_in,
                              void* d_out, int out_size) {
    const float* H1 = (const float*)d_in[0];
    const float* H2 = (const float*)d_in[2];
    const float* z1 = (const float*)d_in[4];
    const float* z2 = (const float*)d_in[5];
    float* out = (float*)d_out;

    cudaFuncSetAttribute(fused_kernel, cudaFuncAttributeMaxDynamicSharedMemorySize, SMEM_BYTES);
    fused_kernel<<<GRID_TOTAL, 256, SMEM_BYTES>>>(H1, H2, z1, z2, out);
}

// round 8
// speedup vs baseline: 4.3273x; 1.1462x over previous
#include <cuda_runtime.h>
#include <cuda_bf16.h>
#include <math.h>
#include <stdint.h>

#define NG   128
#define NPG  256
#define DF   128
#define KB   16
#define VIEWS 256
#define GRID_TOTAL (VIEWS + 16)

#define HQST 136             // int8 H row stride in BYTES (128 + 8 pad; /8 ok, bank-clean)
#define ZST  133             // ntx fp32 row stride (conflict-free)

// topo smem layout (float offsets)
#define F_HQ   0             // 256*136 B = 8704 floats (aliased as reduce buf later)
#define F_CNT  8704          // 8*256 u32 per-warp counters
#define F_SQI  10752         // 256 ints (scaled squared norms, x256)
// ntx smem layout
#define N_RA   0
#define N_ZB   2128
#define N_SIM  19152
#define N_RR   23248
#define SMEM_FLOATS 23264
#define SMEM_BYTES  (SMEM_FLOATS * 4)   // 93056 B -> 2 CTAs/SM

typedef unsigned u32;

__device__ unsigned g_done = 0;
__device__ float g_sig[VIEWS * KB];
__device__ float g_ntx[16];

__device__ __forceinline__ float ex2f(float x) {
    float r; asm("ex2.approx.f32 %0, %1;" : "=f"(r) : "f"(x)); return r;
}

// ---------------------------------------------------------------------------
// Gram quadrant pass, int8 DP4A (4 MACs/instr).
// rows rb+ty+16*ii, cols cb+tx+16*jj ; DIAG: compute cells jj>=ii only,
// emit entries with j>i.
// ---------------------------------------------------------------------------
template<bool DIAG>
__device__ __forceinline__ void gram_pass(const char* __restrict__ Hq,
                                          const int* __restrict__ sqi,
                                          u32* __restrict__ cnt,
                                          int rb, int cb, int tx, int ty, int wid)
{
    int acc[8][8];
    #pragma unroll
    for (int i = 0; i < 8; i++)
        #pragma unroll
        for (int j = 0; j < 8; j++) acc[i][j] = 0;

    const int r0 = rb + ty;
    const int c0 = cb + tx;

    for (int kk = 0; kk < DF; kk += 8) {
        uint2 A[8];
        #pragma unroll
        for (int ii = 0; ii < 8; ii++)
            A[ii] = *(const uint2*)(Hq + (size_t)(r0 + 16 * ii) * HQST + kk);
        #pragma unroll
        for (int half = 0; half < 2; half++) {
            uint2 B[4];
            #pragma unroll
            for (int j4 = 0; j4 < 4; j4++)
                B[j4] = *(const uint2*)(Hq + (size_t)(c0 + 16 * (4 * half + j4)) * HQST + kk);
            #pragma unroll
            for (int ii = 0; ii < 8; ii++)
                #pragma unroll
                for (int j4 = 0; j4 < 4; j4++) {
                    const int jj = 4 * half + j4;
                    if (!DIAG || jj >= ii) {
                        acc[ii][jj] = __dp4a((int)A[ii].x, (int)B[j4].x, acc[ii][jj]);
                        acc[ii][jj] = __dp4a((int)A[ii].y, (int)B[j4].y, acc[ii][jj]);
                    }
                }
        }
    }

    // epilogue: integer d^2 (x256) -> u8 quant (d^2/4) -> per-warp count
    u32* mycnt = cnt + wid * 256;
    #pragma unroll
    for (int ii = 0; ii < 8; ii++) {
        int i = r0 + 16 * ii;
        int si = sqi[i];
        #pragma unroll
        for (int jj = 0; jj < 8; jj++) {
            if (DIAG && jj < ii) continue;
            int j = c0 + 16 * jj;
            if (!DIAG || j > i) {
                int d2i = si + sqi[j] - 2 * acc[ii][jj];   // = 256 * d^2, >= 0 exactly
                d2i = max(d2i, 0);
                u32 q = __float2uint_rn((float)d2i * (1.0f / 1024.0f));
                q = min(q, 255u);
                atomicAdd(&mycnt[q], 1u);
            }
        }
    }
}

// ---------------------------------------------------------------------------
// Topo body: one CTA per graph-view.
// ---------------------------------------------------------------------------
__device__ __forceinline__ void topo_body(float* sm, int t, int v,
                                          const float* __restrict__ H1,
                                          const float* __restrict__ H2)
{
    char* Hq   = (char*)sm;
    u32*  cnt  = (u32*)(sm + F_CNT);
    int*  sqi  = (int*)(sm + F_SQI);
    float* red = sm;                       // aliases Hq; used only after Gram

    const int wid = t >> 5;
    const int tx = t & 15, ty = t >> 4;

    // zero per-warp counters
    #pragma unroll
    for (int i = 0; i < 8; i++) cnt[t + 256 * i] = 0;

    const float* Hsrc = (v < NG) ? (H1 + (size_t)v * NPG * DF)
                                 : (H2 + (size_t)(v - NG) * NPG * DF);

    // stage row t as int8 (scale 16); integer squared norm via dp4a
    {
        const float4* src = (const float4*)(Hsrc + (size_t)t * DF);
        u32* dst = (u32*)(Hq + (size_t)t * HQST);
        int ss = 0;
        #pragma unroll
        for (int m = 0; m < 32; m++) {
            float4 val = src[m];
            int q0 = __float2int_rn(val.x * 16.0f);
            int q1 = __float2int_rn(val.y * 16.0f);
            int q2 = __float2int_rn(val.z * 16.0f);
            int q3 = __float2int_rn(val.w * 16.0f);
            q0 = max(-127, min(127, q0)); q1 = max(-127, min(127, q1));
            q2 = max(-127, min(127, q2)); q3 = max(-127, min(127, q3));
            u32 w = (u32)(q0 & 255) | ((u32)(q1 & 255) << 8)
                  | ((u32)(q2 & 255) << 16) | ((u32)(q3 & 255) << 24);
            dst[m] = w;
            ss = __dp4a((int)w, (int)w, ss);
        }
        sqi[t] = ss;
    }
    __syncthreads();

    gram_pass<false>(Hq, sqi, cnt, 0,   128, tx, ty, wid);
    gram_pass<true >(Hq, sqi, cnt, 0,   0,   tx, ty, wid);
    gram_pass<true >(Hq, sqi, cnt, 128, 128, tx, ty, wid);
    __syncthreads();

    // merge per-warp counters; mean from quantized distances d_q = 2*sqrt(q)
    u32 c_t = 0;
    #pragma unroll
    for (int w = 0; w < 8; w++) c_t += cnt[w * 256 + t];
    float rt2 = 2.0f * sqrtf((float)t);
    red[t] = (float)c_t * rt2;
    __syncthreads();
    for (int s = 128; s > 0; s >>= 1) {
        if (t < s) red[t] += red[t + s];
        __syncthreads();
    }
    float mean = (2.0f * red[0] + 2.56e-4f) * (1.0f / 65536.0f);
    const float Sc = 4.5297165f;           // sqrt(0.5*log2e)/sigma, sigma = 3/16
    const float CS = 0.2f * Sc;
    float invmSc = Sc / (mean + 1e-8f);
    __syncthreads();                       // before reusing red

    // per-q bin weights (16 exp2 per thread, scaled by count)
    float xs = rt2 * invmSc;
    float fc = (float)c_t;
    #pragma unroll
    for (int k = 0; k < KB; k++) {
        float u = xs - CS * (float)k;
        red[t * KB + k] = fc * ex2f(-u * u);
    }
    __syncthreads();
    for (int s = 128; s > 0; s >>= 1) {
        if (t < s) {
            #pragma unroll
            for (int k = 0; k < KB; k++) red[t * KB + k] += red[(t + s) * KB + k];
        }
        __syncthreads();
    }
    if (t == 0) {
        float xd = 1e-6f * invmSc;         // normalized diagonal distance
        float tot = 0.f, bins[KB];
        #pragma unroll
        for (int k = 0; k < KB; k++) {
            float u = xd - CS * (float)k;
            bins[k] = 2.0f * red[k] + 256.0f * ex2f(-u * u);
            tot += bins[k];
        }
        float inv = 1.0f / (tot + 1e-8f);
        #pragma unroll
        for (int k = 0; k < KB; k++) g_sig[v * KB + k] = bins[k] * inv;
    }
}

// ---------------------------------------------------------------------------
// NT-Xent body: CTA b -> sim rows [16b,16b+16); cols staged in 2 passes.
// ---------------------------------------------------------------------------
__device__ __forceinline__ void ntx_norm_row(const float* __restrict__ z1,
                                             const float* __restrict__ z2,
                                             int r, float* dst)
{
    const float* src = (r < NG) ? (z1 + (size_t)r * DF) : (z2 + (size_t)(r - NG) * DF);
    float ss = 0.f;
    #pragma unroll 8
    for (int k = 0; k < DF; k++) { float x = src[k]; ss = fmaf(x, x, ss); }
    float inv = 1.0f / (sqrtf(ss) + 1e-8f);
    #pragma unroll 8
    for (int k = 0; k < DF; k++) dst[k] = src[k] * inv;
}

__device__ __forceinline__ void ntx_body(float* sm, int t, int b,
                                         const float* __restrict__ z1,
                                         const float* __restrict__ z2)
{
    float* Ra     = sm + N_RA;
    float* Zb     = sm + N_ZB;
    float* simbuf = sm + N_SIM;
    float* rowred = sm + N_RR;
    const int rowbase = b * 16;
    const int tx = t & 31, ty = t >> 5;

    for (int p = 0; p < 2; p++) {
        if (p) __syncthreads();            // Zb reuse barrier
        if (t < 128)               ntx_norm_row(z1, z2, 128 * p + t, Zb + (size_t)t * ZST);
        if (p == 0 && t >= 128 && t < 144)
            ntx_norm_row(z1, z2, rowbase + (t - 128), Ra + (size_t)(t - 128) * ZST);
        __syncthreads();

        float acc[2][4];
        #pragma unroll
        for (int a = 0; a < 2; a++)
            #pragma unroll
            for (int c = 0; c < 4; c++) acc[a][c] = 0.f;

        const float* ra0 = Ra + (size_t)(2 * ty) * ZST;
        const float* ra1 = ra0 + ZST;
        #pragma unroll 4
        for (int k = 0; k < DF; k++) {
            float a0 = ra0[k], a1 = ra1[k];
            #pragma unroll
            for (int jj = 0; jj < 4; jj++) {
                float bb = Zb[(size_t)(tx + 32 * jj) * ZST + k];
                acc[0][jj] = fmaf(a0, bb, acc[0][jj]);
                acc[1][jj] = fmaf(a1, bb, acc[1][jj]);
            }
        }
        #pragma unroll
        for (int a = 0; a < 2; a++) {
            int li = 2 * ty + a;
            int gi = rowbase + li;
            #pragma unroll
            for (int jj = 0; jj < 4; jj++) {
                int gj = 128 * p + tx + 32 * jj;
                float s = acc[a][jj] * 2.0f;     // 1/TEMP
                if (gi == gj) s = -1e9f;
                simbuf[li * 256 + gj] = s;
            }
        }
    }
    __syncthreads();

    int w = t >> 5, l = t & 31;
    for (int r = w * 2; r < w * 2 + 2; r++) {
        float mx = -1e30f;
        for (int c = l; c < 256; c += 32) mx = fmaxf(mx, simbuf[r * 256 + c]);
        #pragma unroll
        for (int off = 16; off > 0; off >>= 1)
            mx = fmaxf(mx, __shfl_xor_sync(0xffffffffu, mx, off));
        float se = 0.f;
        for (int c = l; c < 256; c += 32) se += __expf(simbuf[r * 256 + c] - mx);
        #pragma unroll
        for (int off = 16; off > 0; off >>= 1)
            se += __shfl_xor_sync(0xffffffffu, se, off);
        if (l == 0) {
            int gi = rowbase + r;
            int lab = (gi + 128) & 255;
            rowred[r] = simbuf[r * 256 + lab] - (mx + logf(se));
        }
    }
    __syncthreads();
    if (t == 0) {
        float s = 0.f;
        #pragma unroll
        for (int r = 0; r < 16; r++) s += rowred[r];
        g_ntx[b] = s;
    }
}

// ---------------------------------------------------------------------------
__global__ __launch_bounds__(256, 2) void fused_kernel(const float* __restrict__ H1,
                                                       const float* __restrict__ H2,
                                                       const float* __restrict__ z1,
                                                       const float* __restrict__ z2,
                                                       float* __restrict__ out)
{
    extern __shared__ float sm[];
    __shared__ unsigned rank_s;
    const int t = threadIdx.x;
    const int v = blockIdx.x;

    if (v < VIEWS) topo_body(sm, t, v, H1, H2);
    else           ntx_body(sm, t, v - VIEWS, z1, z2);

    __syncthreads();
    if (t == 0) {
        __threadfence();
        rank_s = atomicAdd(&g_done, 1u);
    }
    __syncthreads();

    if (rank_s == GRID_TOTAL - 1) {
        __threadfence();
        float* red2 = sm;
        float val = 0.f;
        if (t < NG) {
            float s = 0.f;
            #pragma unroll
            for (int k = 0; k < KB; k++) {
                float d = __ldcg(&g_sig[t * KB + k]) - __ldcg(&g_sig[(NG + t) * KB + k]);
                s = fmaf(d, d, s);
            }
            val = s * (1.0f / (float)KB);
        }
        red2[t] = val;
        __syncthreads();
        for (int s = 128; s > 0; s >>= 1) {
            if (t < s) red2[t] += red2[t + s];
            __syncthreads();
        }
        if (t == 0) {
            float topo = red2[0] / (float)NG;
            float sn = 0.f;
            #pragma unroll
            for (int i = 0; i < 16; i++) sn += __ldcg(&g_ntx[i]);
            out[0] = 0.1f * (topo - sn / 256.0f);
            g_done = 0;
        }
    }
}

// ---------------------------------------------------------------------------
extern "C" void kernel_launch(void* const* d_in, const int* in_sizes, int n_in,
                              void* d_out, int out_size) {
    const float* H1 = (const float*)d_in[0];
    const float* H2 = (const float*)d_in[2];
    const float* z1 = (const float*)d_in[4];
    const float* z2 = (const float*)d_in[5];
    float* out = (float*)d_out;

    cudaFuncSetAttribute(fused_kernel, cudaFuncAttributeMaxDynamicSharedMemorySize, SMEM_BYTES);
    fused_kernel<<<GRID_TOTAL, 256, SMEM_BYTES>>>(H1, H2, z1, z2, out);
}